// round 2
// baseline (speedup 1.0000x reference)
#include <cuda_runtime.h>
#include <cuda_bf16.h>
#include <math.h>

// Problem constants (fixed shapes for this problem instance)
#define NN 50000
#define EE 800000
#define HH 4
#define FF 64
#define CC 256   // H*F == CIN

// ---------------- device scratch (static, no allocation) ----------------
__device__ float    g_xcomb [(size_t)NN*CC];
__device__ float    g_xl    [(size_t)NN*CC];
__device__ float    g_xr    [(size_t)NN*CC];
__device__ float    g_ident [(size_t)NN*CC];
__device__ float    g_pre   [(size_t)NN*CC];
__device__ float    g_logits[(size_t)EE*HH];
__device__ float    g_nuv   [(size_t)NN*2];
__device__ unsigned g_maxenc[(size_t)NN*HH];
__device__ float    g_sum   [(size_t)NN*HH];
__device__ int      g_deg   [NN+1];
__device__ int      g_off   [NN+1];
__device__ int      g_cursor[NN+1];
__device__ int      g_csr   [EE];

// ---------------- helpers ----------------
__device__ __forceinline__ float wsum(float v){
#pragma unroll
    for (int o=16;o>0;o>>=1) v += __shfl_xor_sync(0xffffffffu, v, o);
    return v;
}

__device__ __forceinline__ unsigned encf(float f){
    int b = __float_as_int(f);
    return (b >= 0) ? ((unsigned)b | 0x80000000u) : (unsigned)(~b);
}
__device__ __forceinline__ float decf(unsigned u){
    int b = (u & 0x80000000u) ? (int)(u & 0x7fffffffu) : (int)(~u);
    return __int_as_float(b);
}

__device__ __forceinline__ float blockSum256(float v){
    __shared__ float sh[8];
    float s = v;
#pragma unroll
    for (int o=16;o>0;o>>=1) s += __shfl_xor_sync(0xffffffffu, s, o);
    if ((threadIdx.x & 31) == 0) sh[threadIdx.x >> 5] = s;
    __syncthreads();
    float t = sh[0]+sh[1]+sh[2]+sh[3]+sh[4]+sh[5]+sh[6]+sh[7];
    __syncthreads();
    return t;
}

// ---------------- kernels ----------------
__global__ void k_init(){
    int i = blockIdx.x*blockDim.x + threadIdx.x;
    int stride = gridDim.x*blockDim.x;
    for (int j=i; j<NN*HH; j+=stride){ g_maxenc[j]=0u; g_sum[j]=0.f; }
    for (int j=i; j<NN+1;  j+=stride){ g_deg[j]=0; }
}

// positional encoder + build x_comb. One warp per node.
__global__ void k_pos(const float* __restrict__ x, const float* __restrict__ kpts,
                      const float* __restrict__ pts,
                      const float* __restrict__ w1, const float* __restrict__ b1,
                      const float* __restrict__ g1, const float* __restrict__ bn1,
                      const float* __restrict__ w2, const float* __restrict__ b2,
                      const float* __restrict__ g2, const float* __restrict__ bn2)
{
    int node = (blockIdx.x*blockDim.x + threadIdx.x) >> 5;
    int lane = threadIdx.x & 31;
    if (node >= NN) return;
    float u  = kpts[node*2+0] * (1.f/1216.f);
    float v  = kpts[node*2+1] * (1.f/352.f);
    float dep = fminf(fmaxf(pts[node*3+2], 0.1f), 100.f);
    if (lane == 0){ g_nuv[node*2]=u; g_nuv[node*2+1]=v; }

    // layer 1: 3 -> 32, LN, SiLU
    float a = w1[lane*3+0]*u + w1[lane*3+1]*v + w1[lane*3+2]*dep + b1[lane];
    float m = wsum(a) * (1.f/32.f);
    float d0 = a - m;
    float var = wsum(d0*d0) * (1.f/32.f);
    float hn = d0 * rsqrtf(var + 1e-5f) * g1[lane] + bn1[lane];
    float h = hn / (1.f + expf(-hn));

    // layer 2: 32 -> 64, LN
    float acc0 = b2[lane], acc1 = b2[lane+32];
#pragma unroll
    for (int k=0;k<32;k++){
        float hk = __shfl_sync(0xffffffffu, h, k);
        acc0 += hk * w2[lane*32 + k];
        acc1 += hk * w2[(lane+32)*32 + k];
    }
    float m2 = wsum(acc0 + acc1) * (1.f/64.f);
    float e0 = acc0 - m2, e1 = acc1 - m2;
    float var2 = wsum(e0*e0 + e1*e1) * (1.f/64.f);
    float rs = rsqrtf(var2 + 1e-5f);
    float p0 = e0*rs*g2[lane]    + bn2[lane];
    float p1 = e1*rs*g2[lane+32] + bn2[lane+32];

    size_t base = (size_t)node * CC;
    g_xcomb[base + 192 + lane] = p0;
    g_xcomb[base + 224 + lane] = p1;
#pragma unroll
    for (int j=lane; j<192; j+=32) g_xcomb[base + j] = x[(size_t)node*192 + j];
}

// tiled SGEMM: C[m][c] = sum_k A[m][k]*W[c][k] + bias[c], K = 256
__global__ void k_sgemm(const float* __restrict__ A, const float* __restrict__ W,
                        const float* __restrict__ bias, float* __restrict__ C, int M)
{
    __shared__ float As[16][64];
    __shared__ float Bs[16][64];
    int m0 = blockIdx.x * 64;
    int c0 = blockIdx.y * 64;
    int t  = threadIdx.x;              // 256
    int tx = t & 15, ty = t >> 4;
    int lr = t >> 2, lq = t & 3;

    float acc[4][4];
#pragma unroll
    for (int i=0;i<4;i++)
#pragma unroll
        for (int j=0;j<4;j++) acc[i][j]=0.f;

    for (int k0=0; k0<CC; k0+=16){
        float4 av = make_float4(0.f,0.f,0.f,0.f);
        int am = m0 + lr;
        if (am < M) av = *(const float4*)&A[(size_t)am*CC + k0 + lq*4];
        As[lq*4+0][lr]=av.x; As[lq*4+1][lr]=av.y; As[lq*4+2][lr]=av.z; As[lq*4+3][lr]=av.w;
        float4 wv = *(const float4*)&W[(size_t)(c0+lr)*CC + k0 + lq*4];
        Bs[lq*4+0][lr]=wv.x; Bs[lq*4+1][lr]=wv.y; Bs[lq*4+2][lr]=wv.z; Bs[lq*4+3][lr]=wv.w;
        __syncthreads();
#pragma unroll
        for (int k=0;k<16;k++){
            float4 a = *(const float4*)&As[k][ty*4];
            float4 b = *(const float4*)&Bs[k][tx*4];
            acc[0][0]+=a.x*b.x; acc[0][1]+=a.x*b.y; acc[0][2]+=a.x*b.z; acc[0][3]+=a.x*b.w;
            acc[1][0]+=a.y*b.x; acc[1][1]+=a.y*b.y; acc[1][2]+=a.y*b.z; acc[1][3]+=a.y*b.w;
            acc[2][0]+=a.z*b.x; acc[2][1]+=a.z*b.y; acc[2][2]+=a.z*b.z; acc[2][3]+=a.z*b.w;
            acc[3][0]+=a.w*b.x; acc[3][1]+=a.w*b.y; acc[3][2]+=a.w*b.z; acc[3][3]+=a.w*b.w;
        }
        __syncthreads();
    }
#pragma unroll
    for (int i=0;i<4;i++){
        int m = m0 + ty*4 + i;
        if (m >= M) continue;
#pragma unroll
        for (int j=0;j<4;j++){
            int c = c0 + tx*4 + j;
            C[(size_t)m*CC + c] = acc[i][j] + bias[c];
        }
    }
}

// edge_attr output + degree histogram
__global__ void k_edgeattr(const int* __restrict__ ei, float* __restrict__ ea)
{
    int e = blockIdx.x*blockDim.x + threadIdx.x;
    if (e >= EE) return;
    int s = ei[e], d = ei[EE + e];
    float r0 = g_nuv[d*2+0] - g_nuv[s*2+0];
    float r1 = g_nuv[d*2+1] - g_nuv[s*2+1];
    float dist = sqrtf(r0*r0 + r1*r1);
    ea[(size_t)e*3+0] = r0;
    ea[(size_t)e*3+1] = r1;
    ea[(size_t)e*3+2] = dist;
    atomicAdd(&g_deg[d], 1);
}

// single-block exclusive scan of degrees -> offsets (+cursor copy)
__global__ void k_scan()
{
    __shared__ int sh[1024];
    int t = threadIdx.x;
    int carry = 0;
    for (int base=0; base<NN; base+=1024){
        int v = (base+t < NN) ? g_deg[base+t] : 0;
        sh[t] = v;
        __syncthreads();
        for (int ofs=1; ofs<1024; ofs<<=1){
            int a = (t >= ofs) ? sh[t-ofs] : 0;
            __syncthreads();
            sh[t] += a;
            __syncthreads();
        }
        int incl  = sh[t];
        int total = sh[1023];
        __syncthreads();
        if (base+t < NN){
            int ex = carry + incl - v;
            g_off[base+t] = ex;
            g_cursor[base+t] = ex;
        }
        carry += total;
    }
    if (t == 0) g_off[NN] = carry;
}

__global__ void k_scatter(const int* __restrict__ ei)
{
    int e = blockIdx.x*blockDim.x + threadIdx.x;
    if (e >= EE) return;
    int d = ei[EE + e];
    int pos = atomicAdd(&g_cursor[d], 1);
    g_csr[pos] = e;
}

// per-edge attention logits; one warp per edge
__global__ void k_logits(const int* __restrict__ ei,
                         const float* __restrict__ lew, const float* __restrict__ att)
{
    __shared__ float s_lew[768];
    __shared__ float s_att[256];
    int t = threadIdx.x;
    s_att[t] = att[t];
    s_lew[t]       = lew[t];
    s_lew[t + 256] = lew[t + 256];
    s_lew[t + 512] = lew[t + 512];
    __syncthreads();

    int e = blockIdx.x*8 + (t >> 5);
    if (e >= EE) return;
    int lane = t & 31;
    int s = ei[e], d = ei[EE + e];

    float r0 = g_nuv[d*2+0] - g_nuv[s*2+0];
    float r1 = g_nuv[d*2+1] - g_nuv[s*2+1];
    float dist = sqrtf(r0*r0 + r1*r1);

    const float4* xl4 = (const float4*)(g_xl + (size_t)s*CC);
    const float4* xr4 = (const float4*)(g_xr + (size_t)d*CC);
    float4 a0 = xl4[lane*2], a1 = xl4[lane*2+1];
    float4 b0 = xr4[lane*2], b1 = xr4[lane*2+1];
    float xs[8] = { a0.x+b0.x, a0.y+b0.y, a0.z+b0.z, a0.w+b0.w,
                    a1.x+b1.x, a1.y+b1.y, a1.z+b1.z, a1.w+b1.w };

    float part = 0.f;
    int c0 = lane*8;
#pragma unroll
    for (int j=0;j<8;j++){
        int c = c0 + j;
        float ee2 = r0*s_lew[c*3+0] + r1*s_lew[c*3+1] + dist*s_lew[c*3+2];
        float z = xs[j] + ee2;
        z = (z > 0.f) ? z : 0.2f*z;
        part += z * s_att[c];
    }
    part += __shfl_xor_sync(0xffffffffu, part, 4);
    part += __shfl_xor_sync(0xffffffffu, part, 2);
    part += __shfl_xor_sync(0xffffffffu, part, 1);
    if ((lane & 7) == 0){
        int h = lane >> 3;
        g_logits[(size_t)e*HH + h] = part;
        atomicMax(&g_maxenc[d*HH + h], encf(part));
    }
}

__global__ void k_exp(const int* __restrict__ ei)
{
    int e = blockIdx.x*blockDim.x + threadIdx.x;
    if (e >= EE) return;
    int d = ei[EE + e];
    float4 lg = *(float4*)(g_logits + (size_t)e*HH);
    float4 ex;
    ex.x = expf(lg.x - decf(g_maxenc[d*HH+0]));
    ex.y = expf(lg.y - decf(g_maxenc[d*HH+1]));
    ex.z = expf(lg.z - decf(g_maxenc[d*HH+2]));
    ex.w = expf(lg.w - decf(g_maxenc[d*HH+3]));
    *(float4*)(g_logits + (size_t)e*HH) = ex;
    atomicAdd(&g_sum[d*HH+0], ex.x);
    atomicAdd(&g_sum[d*HH+1], ex.y);
    atomicAdd(&g_sum[d*HH+2], ex.z);
    atomicAdd(&g_sum[d*HH+3], ex.w);
}

__global__ void k_alpha(const int* __restrict__ ei, float* __restrict__ alpha_out)
{
    int e = blockIdx.x*blockDim.x + threadIdx.x;
    if (e >= EE) return;
    int d = ei[EE + e];
    float4 ex = *(float4*)(g_logits + (size_t)e*HH);
    float4 al;
    al.x = ex.x / (g_sum[d*HH+0] + 1e-16f);
    al.y = ex.y / (g_sum[d*HH+1] + 1e-16f);
    al.z = ex.z / (g_sum[d*HH+2] + 1e-16f);
    al.w = ex.w / (g_sum[d*HH+3] + 1e-16f);
    *(float4*)(alpha_out + (size_t)e*HH) = al;
}

// CSR gather-aggregation + LN + residual + SiLU  (one block per dst node)
__global__ void k_agg(const int* __restrict__ ei, const float* __restrict__ alpha,
                      const float* __restrict__ convb, const float* __restrict__ ng,
                      const float* __restrict__ nb)
{
    int n = blockIdx.x;
    int c = threadIdx.x;        // 256
    int h = c >> 6;
    int st = g_off[n], en = g_off[n+1];
    float acc = 0.f;
    for (int i=st; i<en; i++){
        int e = g_csr[i];
        int s = ei[e];
        acc += alpha[(size_t)e*HH + h] * g_xl[(size_t)s*CC + c];
    }
    float v = acc + convb[c];
    float mean = blockSum256(v) * (1.f/256.f);
    float dv = v - mean;
    float var = blockSum256(dv*dv) * (1.f/256.f);
    float o = dv * rsqrtf(var + 1e-5f) * ng[c] + nb[c];
    float tt = o + g_ident[(size_t)n*CC + c];
    g_pre[(size_t)n*CC + c] = tt / (1.f + expf(-tt));
}

// ---------------- launch ----------------
extern "C" void kernel_launch(void* const* d_in, const int* in_sizes, int n_in,
                              void* d_out, int out_size)
{
    const float* x        = (const float*)d_in[0];
    const float* kpts     = (const float*)d_in[1];
    const float* pts3d    = (const float*)d_in[2];
    const float* pe_w1    = (const float*)d_in[3];
    const float* pe_b1    = (const float*)d_in[4];
    const float* pe_g1    = (const float*)d_in[5];
    const float* pe_bn1   = (const float*)d_in[6];
    const float* pe_w2    = (const float*)d_in[7];
    const float* pe_b2    = (const float*)d_in[8];
    const float* pe_g2    = (const float*)d_in[9];
    const float* pe_bn2   = (const float*)d_in[10];
    const float* lin_l_w  = (const float*)d_in[11];
    const float* lin_l_b  = (const float*)d_in[12];
    const float* lin_r_w  = (const float*)d_in[13];
    const float* lin_r_b  = (const float*)d_in[14];
    const float* lin_edge = (const float*)d_in[15];
    const float* att      = (const float*)d_in[16];
    const float* conv_b   = (const float*)d_in[17];
    const float* norm_g   = (const float*)d_in[18];
    const float* norm_b   = (const float*)d_in[19];
    const float* res_w    = (const float*)d_in[20];
    const float* res_b    = (const float*)d_in[21];
    const float* proj_w   = (const float*)d_in[22];
    const float* proj_b   = (const float*)d_in[23];
    const int*   ei       = (const int*)d_in[24];

    float* out       = (float*)d_out;
    float* alpha_out = out + (size_t)NN*CC;          // [E,4]
    float* ea_out    = alpha_out + (size_t)EE*HH;    // [E,3]

    float *p_xcomb, *p_xl, *p_xr, *p_ident, *p_pre;
    cudaGetSymbolAddress((void**)&p_xcomb, g_xcomb);
    cudaGetSymbolAddress((void**)&p_xl,    g_xl);
    cudaGetSymbolAddress((void**)&p_xr,    g_xr);
    cudaGetSymbolAddress((void**)&p_ident, g_ident);
    cudaGetSymbolAddress((void**)&p_pre,   g_pre);

    k_init<<<256, 256>>>();
    k_pos<<<(NN + 7)/8, 256>>>(x, kpts, pts3d,
                               pe_w1, pe_b1, pe_g1, pe_bn1,
                               pe_w2, pe_b2, pe_g2, pe_bn2);

    dim3 gg((NN + 63)/64, CC/64);
    k_sgemm<<<gg, 256>>>(p_xcomb, lin_l_w, lin_l_b, p_xl,    NN);
    k_sgemm<<<gg, 256>>>(p_xcomb, lin_r_w, lin_r_b, p_xr,    NN);
    k_sgemm<<<gg, 256>>>(p_xcomb, res_w,   res_b,   p_ident, NN);

    k_edgeattr<<<(EE + 255)/256, 256>>>(ei, ea_out);
    k_scan<<<1, 1024>>>();
    k_scatter<<<(EE + 255)/256, 256>>>(ei);

    k_logits<<<(EE + 7)/8, 256>>>(ei, lin_edge, att);
    k_exp<<<(EE + 255)/256, 256>>>(ei);
    k_alpha<<<(EE + 255)/256, 256>>>(ei, alpha_out);

    k_agg<<<NN, 256>>>(ei, alpha_out, conv_b, norm_g, norm_b);
    k_sgemm<<<gg, 256>>>(p_pre, proj_w, proj_b, out, NN);
}

// round 3
// speedup vs baseline: 1.2855x; 1.2855x over previous
#include <cuda_runtime.h>
#include <cuda_bf16.h>
#include <mma.h>
#include <math.h>

using namespace nvcuda;

// Problem constants (fixed shapes for this problem instance)
#define NN 50000
#define EE 800000
#define HH 4
#define FF 64
#define CC 256   // H*F == CIN

// ---------------- device scratch (static, no allocation) ----------------
__device__ float    g_xcomb [(size_t)NN*CC];
__device__ float    g_xl    [(size_t)NN*CC];
__device__ float    g_xr    [(size_t)NN*CC];
__device__ float    g_ident [(size_t)NN*CC];
__device__ float    g_pre   [(size_t)NN*CC];
__device__ float    g_logits[(size_t)EE*HH];
__device__ float    g_nuv   [(size_t)NN*2];
__device__ unsigned g_maxenc[(size_t)NN*HH];
__device__ float    g_sum   [(size_t)NN*HH];
__device__ int      g_deg   [NN+1];
__device__ int      g_off   [NN+1];
__device__ int      g_cursor[NN+1];
__device__ int      g_csr   [EE];

// ---------------- helpers ----------------
__device__ __forceinline__ float wsum(float v){
#pragma unroll
    for (int o=16;o>0;o>>=1) v += __shfl_xor_sync(0xffffffffu, v, o);
    return v;
}

__device__ __forceinline__ unsigned encf(float f){
    int b = __float_as_int(f);
    return (b >= 0) ? ((unsigned)b | 0x80000000u) : (unsigned)(~b);
}
__device__ __forceinline__ float decf(unsigned u){
    int b = (u & 0x80000000u) ? (int)(u & 0x7fffffffu) : (int)(~u);
    return __int_as_float(b);
}

__device__ __forceinline__ float blockSum256(float v){
    __shared__ float sh[8];
    float s = v;
#pragma unroll
    for (int o=16;o>0;o>>=1) s += __shfl_xor_sync(0xffffffffu, s, o);
    if ((threadIdx.x & 31) == 0) sh[threadIdx.x >> 5] = s;
    __syncthreads();
    float t = sh[0]+sh[1]+sh[2]+sh[3]+sh[4]+sh[5]+sh[6]+sh[7];
    __syncthreads();
    return t;
}

// ---------------- kernels ----------------
__global__ void k_init(){
    int i = blockIdx.x*blockDim.x + threadIdx.x;
    int stride = gridDim.x*blockDim.x;
    for (int j=i; j<NN*HH; j+=stride){ g_maxenc[j]=0u; g_sum[j]=0.f; }
    for (int j=i; j<NN+1;  j+=stride){ g_deg[j]=0; }
}

// positional encoder + build x_comb. One warp per node.
__global__ void k_pos(const float* __restrict__ x, const float* __restrict__ kpts,
                      const float* __restrict__ pts,
                      const float* __restrict__ w1, const float* __restrict__ b1,
                      const float* __restrict__ g1, const float* __restrict__ bn1,
                      const float* __restrict__ w2, const float* __restrict__ b2,
                      const float* __restrict__ g2, const float* __restrict__ bn2)
{
    int node = (blockIdx.x*blockDim.x + threadIdx.x) >> 5;
    int lane = threadIdx.x & 31;
    if (node >= NN) return;
    float u  = kpts[node*2+0] * (1.f/1216.f);
    float v  = kpts[node*2+1] * (1.f/352.f);
    float dep = fminf(fmaxf(pts[node*3+2], 0.1f), 100.f);
    if (lane == 0){ g_nuv[node*2]=u; g_nuv[node*2+1]=v; }

    // layer 1: 3 -> 32, LN, SiLU
    float a = w1[lane*3+0]*u + w1[lane*3+1]*v + w1[lane*3+2]*dep + b1[lane];
    float m = wsum(a) * (1.f/32.f);
    float d0 = a - m;
    float var = wsum(d0*d0) * (1.f/32.f);
    float hn = d0 * rsqrtf(var + 1e-5f) * g1[lane] + bn1[lane];
    float h = hn / (1.f + expf(-hn));

    // layer 2: 32 -> 64, LN
    float acc0 = b2[lane], acc1 = b2[lane+32];
#pragma unroll
    for (int k=0;k<32;k++){
        float hk = __shfl_sync(0xffffffffu, h, k);
        acc0 += hk * w2[lane*32 + k];
        acc1 += hk * w2[(lane+32)*32 + k];
    }
    float m2 = wsum(acc0 + acc1) * (1.f/64.f);
    float e0 = acc0 - m2, e1 = acc1 - m2;
    float var2 = wsum(e0*e0 + e1*e1) * (1.f/64.f);
    float rs = rsqrtf(var2 + 1e-5f);
    float p0 = e0*rs*g2[lane]    + bn2[lane];
    float p1 = e1*rs*g2[lane+32] + bn2[lane+32];

    size_t base = (size_t)node * CC;
    g_xcomb[base + 192 + lane] = p0;
    g_xcomb[base + 224 + lane] = p1;
#pragma unroll
    for (int j=lane; j<192; j+=32) g_xcomb[base + j] = x[(size_t)node*192 + j];
}

// ---------------- tf32 tensor-core GEMM ----------------
// C[m][c] = sum_k A[m][k] * W[c][k] + bias[c]
// Up to 3 output matrices selected by blockIdx.y>>2 (each 256 cols wide = 4 block-cols).
// Block tile: 64 rows x 64 cols, 256 threads (8 warps), wmma 16x16x8 tf32.
__global__ void k_tcgemm(const float* __restrict__ A,
                         const float* __restrict__ W0, const float* __restrict__ W1,
                         const float* __restrict__ W2,
                         const float* __restrict__ b0, const float* __restrict__ b1,
                         const float* __restrict__ b2,
                         float* __restrict__ C0, float* __restrict__ C1,
                         float* __restrict__ C2, int M)
{
    __shared__ float As[64][36];
    __shared__ float Ws[64][36];
    __shared__ float Cs[64][64];

    int t = threadIdx.x;
    int m0 = blockIdx.x * 64;
    int tgt = blockIdx.y >> 2;
    int c0l = (blockIdx.y & 3) * 64;

    const float* W    = (tgt == 0) ? W0 : (tgt == 1) ? W1 : W2;
    const float* bias = (tgt == 0) ? b0 : (tgt == 1) ? b1 : b2;
    float*       C    = (tgt == 0) ? C0 : (tgt == 1) ? C1 : C2;

    int warp = t >> 5;
    int r  = (warp >> 1) * 16;        // warp row tile origin (0,16,32,48)
    int cb = (warp & 1) * 32;         // warp col tile origin (0,32), two 16-col tiles

    wmma::fragment<wmma::accumulator, 16, 16, 8, float> acc0f, acc1f;
    wmma::fill_fragment(acc0f, 0.f);
    wmma::fill_fragment(acc1f, 0.f);

    for (int k0 = 0; k0 < CC; k0 += 32){
        // load A tile 64x32 and W tile 64x32 (float4 per thread x2)
#pragma unroll
        for (int j = 0; j < 2; j++){
            int id  = t + j * 256;
            int row = id >> 3;
            int col = (id & 7) * 4;
            float4 av = make_float4(0.f,0.f,0.f,0.f);
            if (m0 + row < M)
                av = *(const float4*)&A[(size_t)(m0 + row) * CC + k0 + col];
            *(float4*)&As[row][col] = av;
            float4 wv = *(const float4*)&W[(size_t)(c0l + row) * CC + k0 + col];
            *(float4*)&Ws[row][col] = wv;
        }
        __syncthreads();

#pragma unroll
        for (int kk = 0; kk < 32; kk += 8){
            wmma::fragment<wmma::matrix_a, 16, 16, 8, wmma::precision::tf32, wmma::row_major> af;
            wmma::fragment<wmma::matrix_b, 16, 16, 8, wmma::precision::tf32, wmma::col_major> bf0, bf1;
            wmma::load_matrix_sync(af, &As[r][kk], 36);
#pragma unroll
            for (int i = 0; i < af.num_elements; i++) af.x[i] = wmma::__float_to_tf32(af.x[i]);
            wmma::load_matrix_sync(bf0, &Ws[cb][kk], 36);
            wmma::load_matrix_sync(bf1, &Ws[cb + 16][kk], 36);
#pragma unroll
            for (int i = 0; i < bf0.num_elements; i++){
                bf0.x[i] = wmma::__float_to_tf32(bf0.x[i]);
                bf1.x[i] = wmma::__float_to_tf32(bf1.x[i]);
            }
            wmma::mma_sync(acc0f, af, bf0, acc0f);
            wmma::mma_sync(acc1f, af, bf1, acc1f);
        }
        __syncthreads();
    }

    wmma::store_matrix_sync(&Cs[r][cb],      acc0f, 64, wmma::mem_row_major);
    wmma::store_matrix_sync(&Cs[r][cb + 16], acc1f, 64, wmma::mem_row_major);
    __syncthreads();

    // epilogue: add bias, write out
    int ct = t & 63;
    int r0 = t >> 6;
    float bv = bias[c0l + ct];
#pragma unroll
    for (int i = 0; i < 16; i++){
        int row = r0 + i * 4;
        int m = m0 + row;
        if (m < M)
            C[(size_t)m * CC + c0l + ct] = Cs[row][ct] + bv;
    }
}

// edge_attr output + degree histogram
__global__ void k_edgeattr(const int* __restrict__ ei, float* __restrict__ ea)
{
    int e = blockIdx.x*blockDim.x + threadIdx.x;
    if (e >= EE) return;
    int s = ei[e], d = ei[EE + e];
    float r0 = g_nuv[d*2+0] - g_nuv[s*2+0];
    float r1 = g_nuv[d*2+1] - g_nuv[s*2+1];
    float dist = sqrtf(r0*r0 + r1*r1);
    ea[(size_t)e*3+0] = r0;
    ea[(size_t)e*3+1] = r1;
    ea[(size_t)e*3+2] = dist;
    atomicAdd(&g_deg[d], 1);
}

// single-block exclusive scan of degrees -> offsets (+cursor copy), warp-shuffle based
__global__ void k_scan()
{
    __shared__ int warpsum[32];
    __shared__ int warpoff[32];
    int t = threadIdx.x;
    int lane = t & 31, wid = t >> 5;
    int carry = 0;
    for (int base = 0; base < NN; base += 1024){
        int v = (base + t < NN) ? g_deg[base + t] : 0;
        // warp inclusive scan
        int s = v;
#pragma unroll
        for (int o = 1; o < 32; o <<= 1){
            int n = __shfl_up_sync(0xffffffffu, s, o);
            if (lane >= o) s += n;
        }
        if (lane == 31) warpsum[wid] = s;
        __syncthreads();
        if (wid == 0){
            int ws = warpsum[lane];
            int t2 = ws;
#pragma unroll
            for (int o = 1; o < 32; o <<= 1){
                int n = __shfl_up_sync(0xffffffffu, t2, o);
                if (lane >= o) t2 += n;
            }
            warpoff[lane] = t2 - ws;   // exclusive
            if (lane == 31) warpsum[0] = t2;  // tile total
        }
        __syncthreads();
        int tile_total = warpsum[0];
        if (base + t < NN){
            int ex = carry + warpoff[wid] + s - v;
            g_off[base + t] = ex;
            g_cursor[base + t] = ex;
        }
        __syncthreads();
        carry += tile_total;
    }
    if (t == 0) g_off[NN] = carry;
}

__global__ void k_scatter(const int* __restrict__ ei)
{
    int e = blockIdx.x*blockDim.x + threadIdx.x;
    if (e >= EE) return;
    int d = ei[EE + e];
    int pos = atomicAdd(&g_cursor[d], 1);
    g_csr[pos] = e;
}

// per-edge attention logits; one warp per edge
__global__ void k_logits(const int* __restrict__ ei,
                         const float* __restrict__ lew, const float* __restrict__ att)
{
    __shared__ float s_lew[768];
    __shared__ float s_att[256];
    int t = threadIdx.x;
    s_att[t] = att[t];
    s_lew[t]       = lew[t];
    s_lew[t + 256] = lew[t + 256];
    s_lew[t + 512] = lew[t + 512];
    __syncthreads();

    int e = blockIdx.x*8 + (t >> 5);
    if (e >= EE) return;
    int lane = t & 31;
    int s = ei[e], d = ei[EE + e];

    float r0 = g_nuv[d*2+0] - g_nuv[s*2+0];
    float r1 = g_nuv[d*2+1] - g_nuv[s*2+1];
    float dist = sqrtf(r0*r0 + r1*r1);

    const float4* xl4 = (const float4*)(g_xl + (size_t)s*CC);
    const float4* xr4 = (const float4*)(g_xr + (size_t)d*CC);
    float4 a0 = xl4[lane*2], a1 = xl4[lane*2+1];
    float4 b0 = xr4[lane*2], b1 = xr4[lane*2+1];
    float xs[8] = { a0.x+b0.x, a0.y+b0.y, a0.z+b0.z, a0.w+b0.w,
                    a1.x+b1.x, a1.y+b1.y, a1.z+b1.z, a1.w+b1.w };

    float part = 0.f;
    int c0 = lane*8;
#pragma unroll
    for (int j=0;j<8;j++){
        int c = c0 + j;
        float ee2 = r0*s_lew[c*3+0] + r1*s_lew[c*3+1] + dist*s_lew[c*3+2];
        float z = xs[j] + ee2;
        z = (z > 0.f) ? z : 0.2f*z;
        part += z * s_att[c];
    }
    part += __shfl_xor_sync(0xffffffffu, part, 4);
    part += __shfl_xor_sync(0xffffffffu, part, 2);
    part += __shfl_xor_sync(0xffffffffu, part, 1);
    if ((lane & 7) == 0){
        int h = lane >> 3;
        g_logits[(size_t)e*HH + h] = part;
        atomicMax(&g_maxenc[d*HH + h], encf(part));
    }
}

__global__ void k_exp(const int* __restrict__ ei)
{
    int e = blockIdx.x*blockDim.x + threadIdx.x;
    if (e >= EE) return;
    int d = ei[EE + e];
    float4 lg = *(float4*)(g_logits + (size_t)e*HH);
    float4 ex;
    ex.x = expf(lg.x - decf(g_maxenc[d*HH+0]));
    ex.y = expf(lg.y - decf(g_maxenc[d*HH+1]));
    ex.z = expf(lg.z - decf(g_maxenc[d*HH+2]));
    ex.w = expf(lg.w - decf(g_maxenc[d*HH+3]));
    *(float4*)(g_logits + (size_t)e*HH) = ex;
    atomicAdd(&g_sum[d*HH+0], ex.x);
    atomicAdd(&g_sum[d*HH+1], ex.y);
    atomicAdd(&g_sum[d*HH+2], ex.z);
    atomicAdd(&g_sum[d*HH+3], ex.w);
}

__global__ void k_alpha(const int* __restrict__ ei, float* __restrict__ alpha_out)
{
    int e = blockIdx.x*blockDim.x + threadIdx.x;
    if (e >= EE) return;
    int d = ei[EE + e];
    float4 ex = *(float4*)(g_logits + (size_t)e*HH);
    float4 al;
    al.x = ex.x / (g_sum[d*HH+0] + 1e-16f);
    al.y = ex.y / (g_sum[d*HH+1] + 1e-16f);
    al.z = ex.z / (g_sum[d*HH+2] + 1e-16f);
    al.w = ex.w / (g_sum[d*HH+3] + 1e-16f);
    *(float4*)(alpha_out + (size_t)e*HH) = al;
}

// CSR gather-aggregation + LN + residual + SiLU  (one block per dst node)
__global__ void k_agg(const int* __restrict__ ei, const float* __restrict__ alpha,
                      const float* __restrict__ convb, const float* __restrict__ ng,
                      const float* __restrict__ nb)
{
    int n = blockIdx.x;
    int c = threadIdx.x;        // 256
    int h = c >> 6;
    int st = g_off[n], en = g_off[n+1];
    float acc = 0.f;
    for (int i=st; i<en; i++){
        int e = g_csr[i];
        int s = ei[e];
        acc += alpha[(size_t)e*HH + h] * g_xl[(size_t)s*CC + c];
    }
    float v = acc + convb[c];
    float mean = blockSum256(v) * (1.f/256.f);
    float dv = v - mean;
    float var = blockSum256(dv*dv) * (1.f/256.f);
    float o = dv * rsqrtf(var + 1e-5f) * ng[c] + nb[c];
    float tt = o + g_ident[(size_t)n*CC + c];
    g_pre[(size_t)n*CC + c] = tt / (1.f + expf(-tt));
}

// ---------------- launch ----------------
extern "C" void kernel_launch(void* const* d_in, const int* in_sizes, int n_in,
                              void* d_out, int out_size)
{
    const float* x        = (const float*)d_in[0];
    const float* kpts     = (const float*)d_in[1];
    const float* pts3d    = (const float*)d_in[2];
    const float* pe_w1    = (const float*)d_in[3];
    const float* pe_b1    = (const float*)d_in[4];
    const float* pe_g1    = (const float*)d_in[5];
    const float* pe_bn1   = (const float*)d_in[6];
    const float* pe_w2    = (const float*)d_in[7];
    const float* pe_b2    = (const float*)d_in[8];
    const float* pe_g2    = (const float*)d_in[9];
    const float* pe_bn2   = (const float*)d_in[10];
    const float* lin_l_w  = (const float*)d_in[11];
    const float* lin_l_b  = (const float*)d_in[12];
    const float* lin_r_w  = (const float*)d_in[13];
    const float* lin_r_b  = (const float*)d_in[14];
    const float* lin_edge = (const float*)d_in[15];
    const float* att      = (const float*)d_in[16];
    const float* conv_b   = (const float*)d_in[17];
    const float* norm_g   = (const float*)d_in[18];
    const float* norm_b   = (const float*)d_in[19];
    const float* res_w    = (const float*)d_in[20];
    const float* res_b    = (const float*)d_in[21];
    const float* proj_w   = (const float*)d_in[22];
    const float* proj_b   = (const float*)d_in[23];
    const int*   ei       = (const int*)d_in[24];

    float* out       = (float*)d_out;
    float* alpha_out = out + (size_t)NN*CC;          // [E,4]
    float* ea_out    = alpha_out + (size_t)EE*HH;    // [E,3]

    float *p_xcomb, *p_xl, *p_xr, *p_ident, *p_pre;
    cudaGetSymbolAddress((void**)&p_xcomb, g_xcomb);
    cudaGetSymbolAddress((void**)&p_xl,    g_xl);
    cudaGetSymbolAddress((void**)&p_xr,    g_xr);
    cudaGetSymbolAddress((void**)&p_ident, g_ident);
    cudaGetSymbolAddress((void**)&p_pre,   g_pre);

    k_init<<<256, 256>>>();
    k_pos<<<(NN + 7)/8, 256>>>(x, kpts, pts3d,
                               pe_w1, pe_b1, pe_g1, pe_bn1,
                               pe_w2, pe_b2, pe_g2, pe_bn2);

    // fused lin_l + lin_r + res GEMMs (tf32 tensor cores)
    dim3 g3((NN + 63)/64, 12);
    k_tcgemm<<<g3, 256>>>(p_xcomb, lin_l_w, lin_r_w, res_w,
                          lin_l_b, lin_r_b, res_b,
                          p_xl, p_xr, p_ident, NN);

    k_edgeattr<<<(EE + 255)/256, 256>>>(ei, ea_out);
    k_scan<<<1, 1024>>>();
    k_scatter<<<(EE + 255)/256, 256>>>(ei);

    k_logits<<<(EE + 7)/8, 256>>>(ei, lin_edge, att);
    k_exp<<<(EE + 255)/256, 256>>>(ei);
    k_alpha<<<(EE + 255)/256, 256>>>(ei, alpha_out);

    k_agg<<<NN, 256>>>(ei, alpha_out, conv_b, norm_g, norm_b);

    // projector GEMM (single target)
    dim3 g1((NN + 63)/64, 4);
    k_tcgemm<<<g1, 256>>>(p_pre, proj_w, proj_w, proj_w,
                          proj_b, proj_b, proj_b,
                          out, out, out, NN);
}